// round 12
// baseline (speedup 1.0000x reference)
#include <cuda_runtime.h>

#define NN 100000
#define EE 3200000
#define NG 100
#define NPER 1000
#define EPG 32000
#define KTOP 800
#define GEMM_BLOCKS ((NN + 63) / 64)   // 1563

// ---------------- global scratch (static; no cudaMalloc) ----------------
__device__ int    g_off[NN + 1];
__device__ int    g_csr[EE];
__device__ float  g_dis[NN];
__device__ float  g_dis2[NN];
__device__ float  g_f[NN];             // score * dis2 (0 for masked)
__device__ float  g_p[NN];             // h . w_rel
__device__ float  g_hr[NN];            // h . w_root
__device__ float4 g_xw[NN * 4];        // x @ W1 (NO dis)  [N,16]
__device__ float4 g_h4[NN * 4];        // conv1 output     [N,16]

// ---- thread-per-node scalar gather, 2x int4 unrolled, table in SMEM ----
__device__ __forceinline__ float gather_sum_smem(const float* __restrict__ tab,
                                                 int beg, int end, int nbase) {
    float a0 = 0.f, a1 = 0.f, a2 = 0.f, a3 = 0.f;
    int i = beg;
    for (; i < end && (i & 3); i++) a0 += tab[__ldg(&g_csr[i]) - nbase];
    int n4 = (end - i) >> 2;
    const int4* c4 = (const int4*)&g_csr[i];
    int k = 0;
    for (; k + 2 <= n4; k += 2) {
        int4 u = __ldg(&c4[k]);
        int4 w = __ldg(&c4[k + 1]);
        a0 += tab[u.x - nbase];
        a1 += tab[u.y - nbase];
        a2 += tab[u.z - nbase];
        a3 += tab[u.w - nbase];
        a0 += tab[w.x - nbase];
        a1 += tab[w.y - nbase];
        a2 += tab[w.z - nbase];
        a3 += tab[w.w - nbase];
    }
    if (k < n4) {
        int4 u = __ldg(&c4[k]);
        a0 += tab[u.x - nbase];
        a1 += tab[u.y - nbase];
        a2 += tab[u.z - nbase];
        a3 += tab[u.w - nbase];
    }
    for (i += n4 << 2; i < end; i++) a0 += tab[__ldg(&g_csr[i]) - nbase];
    return (a0 + a1) + (a2 + a3);
}

// ============ heterogeneous stage 0: blocks 0..99 = CSR build; rest = GEMM1 ==========
__global__ void __launch_bounds__(1024) k_stage0(const int* __restrict__ src,
                                                 const int* __restrict__ dst,
                                                 const float* __restrict__ x,
                                                 const float* __restrict__ W1) {
    __shared__ float smem_raw[64 * 129 + 2048];   // 41216B, shared by both paths
    int t = threadIdx.x;

    if (blockIdx.x < NG) {
        // ---------------- CSR build (register-cached ranks) ----------------
        int* sdeg = (int*)smem_raw;          // [1024]
        int* soff = (int*)smem_raw + 1024;   // [1024]
        int g = blockIdx.x;
        int ebase = g * EPG, nbase = g * NPER;
        sdeg[t] = 0;
        __syncthreads();
        unsigned pk[32];   // (rank<<16) | local_dst
#pragma unroll
        for (int k = 0; k < 32; k++) {
            int e = t + (k << 10);
            if (e < EPG) {
                int d = dst[ebase + e] - nbase;
                unsigned r = atomicAdd(&sdeg[d], 1);
                pk[k] = (r << 16) | (unsigned)d;
            }
        }
        __syncthreads();
        int v = sdeg[t];
        soff[t] = v;
        __syncthreads();
        for (int d = 1; d < 1024; d <<= 1) {
            int cur = soff[t];
            int add = (t >= d) ? soff[t - d] : 0;
            __syncthreads();
            soff[t] = cur + add;
            __syncthreads();
        }
        int excl = soff[t] - v;
        if (t < NPER) {
            g_off[nbase + t] = ebase + excl;
            g_dis[nbase + t] = rsqrtf((float)(v + 1));
        }
        if (g == NG - 1 && t == 0) g_off[NN] = EE;
        sdeg[t] = excl;
        __syncthreads();
#pragma unroll
        for (int k = 0; k < 32; k++) {
            int e = t + (k << 10);
            if (e < EPG) {
                unsigned p = pk[k];
                int d = p & 0xFFFFu;
                int r = (int)(p >> 16);
                g_csr[ebase + sdeg[d] + r] = src[ebase + e];
            }
        }
    } else {
        // ---------------- GEMM1: xw = x @ W1 (no dis) ----------------
        float* xs = smem_raw;                 // [64*129]
        float* ws = smem_raw + 64 * 129;      // [2048]
        int v0 = (blockIdx.x - NG) * 64;
        for (int i = t; i < 2048; i += 1024) ws[i] = W1[i];
        const float4* x4 = (const float4*)x;
        for (int i = t; i < 64 * 32; i += 1024) {
            int r = i >> 5, c = i & 31;
            int v = v0 + r;
            float4 val = (v < NN) ? x4[(size_t)v * 32 + c] : make_float4(0.f, 0.f, 0.f, 0.f);
            float* p = &xs[r * 129 + c * 4];
            p[0] = val.x; p[1] = val.y; p[2] = val.z; p[3] = val.w;
        }
        __syncthreads();
        int n = t & 63;
        int jg = t >> 6;                      // 0..15, warp-uniform
        float acc = 0.f;
        const float* xr = &xs[n * 129];
#pragma unroll 16
        for (int k = 0; k < 128; k++)
            acc = fmaf(xr[k], ws[k * 16 + jg], acc);
        int v = v0 + n;
        if (v < NN) ((float*)g_xw)[v * 16 + jg] = acc;
    }
}

// ============ conv1: float4 SMEM gather; tile = xw * dis applied at load ============
__global__ void __launch_bounds__(512) k_conv1(const float* __restrict__ b1,
                                               const float* __restrict__ wrel,
                                               const float* __restrict__ wroot) {
    extern __shared__ float tile[];   // [1000][16], = xw * dis
    int g = blockIdx.x >> 2;
    int quarter = blockIdx.x & 3;
    int nbase = g * NPER;
    int tid = threadIdx.x;
    const float4* src4 = (const float4*)&g_xw[nbase * 4];
    float4* t4 = (float4*)tile;
    for (int i = tid; i < NPER * 4; i += 512) {
        int vl = i >> 2;
        float d = g_dis[nbase + vl];
        float4 val = src4[i];
        t4[i] = make_float4(val.x * d, val.y * d, val.z * d, val.w * d);
    }
    __syncthreads();
    int wid = tid >> 5, lane = tid & 31;
    int sub = lane >> 2, c = lane & 3;
    float4 bb = __ldg(&((const float4*)b1)[c]);
    float4 wr = __ldg(&((const float4*)wrel)[c]);
    float4 wo = __ldg(&((const float4*)wroot)[c]);
    int vbeg = quarter * 250, vend = vbeg + 250;
    for (int vl = vbeg + wid; vl < vend; vl += 16) {
        int v = nbase + vl;
        int beg = g_off[v], end = g_off[v + 1];
        float4 acc = make_float4(0.f, 0.f, 0.f, 0.f);
        for (int i = beg + sub; i < end; i += 8) {
            int u = __ldg(&g_csr[i]) - nbase;
            float4 tt = t4[u * 4 + c];
            acc.x += tt.x; acc.y += tt.y; acc.z += tt.z; acc.w += tt.w;
        }
#pragma unroll
        for (int m = 4; m < 32; m <<= 1) {
            acc.x += __shfl_xor_sync(0xffffffffu, acc.x, m);
            acc.y += __shfl_xor_sync(0xffffffffu, acc.y, m);
            acc.z += __shfl_xor_sync(0xffffffffu, acc.z, m);
            acc.w += __shfl_xor_sync(0xffffffffu, acc.w, m);
        }
        float d = g_dis[v];
        float4 cv = t4[vl * 4 + c];
        float4 hv;
        hv.x = fmaxf(fmaf(d, acc.x + cv.x, bb.x), 0.f);
        hv.y = fmaxf(fmaf(d, acc.y + cv.y, bb.y), 0.f);
        hv.z = fmaxf(fmaf(d, acc.z + cv.z, bb.z), 0.f);
        hv.w = fmaxf(fmaf(d, acc.w + cv.w, bb.w), 0.f);
        if (sub == 0) g_h4[v * 4 + c] = hv;
        float pp = hv.x * wr.x + hv.y * wr.y + hv.z * wr.z + hv.w * wr.w;
        float rr = hv.x * wo.x + hv.y * wo.y + hv.z * wo.z + hv.w * wo.w;
        pp += __shfl_xor_sync(0xffffffffu, pp, 1);
        pp += __shfl_xor_sync(0xffffffffu, pp, 2);
        rr += __shfl_xor_sync(0xffffffffu, rr, 1);
        rr += __shfl_xor_sync(0xffffffffu, rr, 2);
        if (lane == 0) { g_p[v] = pp; g_hr[v] = rr; }
    }
}

// ============ topk: score + hybrid bitonic + deg2 (fused) ============
__global__ void __launch_bounds__(1024) k_topk(const float* __restrict__ brel) {
    __shared__ unsigned long long keys[1024];
    __shared__ float p_s[NPER];
    __shared__ float smask[NPER];
    int g = blockIdx.x, t = threadIdx.x;
    int nbase = g * NPER;

    if (t < NPER) p_s[t] = g_p[nbase + t];
    __syncthreads();

    float sc = 0.f;
    if (t < NPER) {
        int v = nbase + t;
        float s = gather_sum_smem(p_s, g_off[v], g_off[v + 1], nbase);
        sc = tanhf(s + g_hr[v] + __ldg(brel));
        unsigned u = __float_as_uint(sc);
        u = (u & 0x80000000u) ? ~u : (u | 0x80000000u);   // monotone float map
        keys[t] = ((unsigned long long)u << 32) | (unsigned)(~t);  // ties: lower idx wins
    } else {
        keys[t] = 0ull;
    }
    __syncthreads();

    for (int k = 2; k <= 1024; k <<= 1) {
        for (int j = k >> 1; j >= 32; j >>= 1) {
            int ixj = t ^ j;
            if (ixj > t) {
                unsigned long long a = keys[t], b = keys[ixj];
                bool up = ((t & k) == 0);
                if ((a > b) == up) { keys[t] = b; keys[ixj] = a; }
            }
            __syncthreads();
        }
        unsigned long long v = keys[t];
        bool up = ((t & k) == 0);
        int jstart = (k >> 1 < 16) ? (k >> 1) : 16;
        for (int j = jstart; j > 0; j >>= 1) {
            unsigned long long o = __shfl_xor_sync(0xffffffffu, v, j);
            bool lower = ((t & j) == 0);
            bool keepmin = (lower == up);
            unsigned long long mn = (v < o) ? v : o;
            unsigned long long mx = (v < o) ? o : v;
            v = keepmin ? mn : mx;
        }
        keys[t] = v;
        __syncthreads();
    }
    if (t >= (1024 - NPER)) {
        unsigned idx = ~(unsigned)(keys[t] & 0xFFFFFFFFull);
        smask[idx] = (t >= 1024 - KTOP) ? 1.0f : 0.0f;
    }
    __syncthreads();

    if (t < NPER) {
        int v = nbase + t;
        float s = gather_sum_smem(smask, g_off[v], g_off[v + 1], nbase);
        float mv = smask[t];
        float d2 = (mv > 0.f) ? rsqrtf(mv + s) : 0.f;
        g_dis2[v] = d2;
        g_f[v] = sc * d2;
    }
}

// ============ conv2 + pool fused: 4 blocks/graph x 512 thr ============
__global__ void __launch_bounds__(512) k_conv2pool(const float* __restrict__ W2,
                                                   const float* __restrict__ b2,
                                                   float* __restrict__ out) {
    extern __shared__ float sm[];
    float* c2  = sm;                 // [16000]
    float* ggs = sm + 16000;         // [4000]
    float* d2s = sm + 20000;         // [256]
    int g = blockIdx.x >> 2;
    int quarter = blockIdx.x & 3;
    int nbase = g * NPER;
    int vbeg = quarter * 250;
    int t = threadIdx.x;

    const float4* h4 = (const float4*)&g_h4[nbase * 4];
    float4* c24 = (float4*)c2;
    for (int i = t; i < NPER * 4; i += 512) {
        int vl = i >> 2;
        float f = __ldg(&g_f[nbase + vl]);
        float4 h = h4[i];
        c24[i] = make_float4(h.x * f, h.y * f, h.z * f, h.w * f);
    }
    if (t < 250) d2s[t] = g_dis2[nbase + vbeg + t];
    __syncthreads();

    int wid = t >> 5, lane = t & 31;
    int sub = lane >> 2, c = lane & 3;
    float4* gg4 = (float4*)ggs;
    for (int vl = vbeg + wid; vl < vbeg + 250; vl += 16) {
        float d2 = d2s[vl - vbeg];
        if (d2 == 0.f) continue;
        int v = nbase + vl;
        int beg = g_off[v], end = g_off[v + 1];
        float4 acc = make_float4(0.f, 0.f, 0.f, 0.f);
        for (int i = beg + sub; i < end; i += 8) {
            int u = __ldg(&g_csr[i]) - nbase;
            float4 tt = c24[u * 4 + c];
            acc.x += tt.x; acc.y += tt.y; acc.z += tt.z; acc.w += tt.w;
        }
#pragma unroll
        for (int m = 4; m < 32; m <<= 1) {
            acc.x += __shfl_xor_sync(0xffffffffu, acc.x, m);
            acc.y += __shfl_xor_sync(0xffffffffu, acc.y, m);
            acc.z += __shfl_xor_sync(0xffffffffu, acc.z, m);
            acc.w += __shfl_xor_sync(0xffffffffu, acc.w, m);
        }
        if (sub == 0) {
            float4 cv = c24[vl * 4 + c];
            gg4[(vl - vbeg) * 4 + c] =
                make_float4(d2 * (acc.x + cv.x), d2 * (acc.y + cv.y),
                            d2 * (acc.z + cv.z), d2 * (acc.w + cv.w));
        }
    }
    __syncthreads();

    {
        int col = t & 255;
        int half = t >> 8;
        float w[16];
#pragma unroll
        for (int m = 0; m < 16; m++) w[m] = __ldg(&W2[m * 256 + col]);
        float bc = __ldg(&b2[col]);
        float acc = 0.f;
        int l0 = half * 125, l1 = l0 + 125;
        for (int l = l0; l < l1; l++) {
            if (d2s[l] != 0.f) {
                const float* gr = &ggs[l * 16];
                float s = bc;
#pragma unroll
                for (int m = 0; m < 16; m++) s = fmaf(gr[m], w[m], s);
                acc += fmaxf(s, 0.f);
            }
        }
        atomicAdd(&out[g * 256 + col], acc * (1.0f / (float)KTOP));
    }
}

// ============ launch ============
extern "C" void kernel_launch(void* const* d_in, const int* in_sizes, int n_in,
                              void* d_out, int out_size) {
    const float* x     = (const float*)d_in[0];
    const int*   ei    = (const int*)d_in[1];
    const float* W1    = (const float*)d_in[3];
    const float* b1    = (const float*)d_in[4];
    const float* wrel  = (const float*)d_in[5];
    const float* brel  = (const float*)d_in[6];
    const float* wroot = (const float*)d_in[7];
    const float* W2    = (const float*)d_in[8];
    const float* b2    = (const float*)d_in[9];
    float* out = (float*)d_out;

    const int* src = ei;
    const int* dst = ei + EE;

    const int TILE_SMEM = NPER * 16 * 4;             // 64000
    const int CP_SMEM   = (20000 + 256) * 4;         // 81024
    cudaFuncSetAttribute(k_conv1, cudaFuncAttributeMaxDynamicSharedMemorySize, TILE_SMEM);
    cudaFuncSetAttribute(k_conv2pool, cudaFuncAttributeMaxDynamicSharedMemorySize, CP_SMEM);

    cudaMemsetAsync(d_out, 0, (size_t)out_size * sizeof(float), 0);

    k_stage0<<<NG + GEMM_BLOCKS, 1024>>>(src, dst, x, W1);
    k_conv1<<<NG * 4, 512, TILE_SMEM>>>(b1, wrel, wroot);
    k_topk<<<NG, 1024>>>(brel);
    k_conv2pool<<<NG * 4, 512, CP_SMEM>>>(W2, b2, out);
}

// round 13
// speedup vs baseline: 1.0867x; 1.0867x over previous
#include <cuda_runtime.h>

#define NN 100000
#define EE 3200000
#define NG 100
#define NPER 1000
#define EPG 32000
#define KTOP 800

// ---------------- global scratch (static; no cudaMalloc) ----------------
__device__ int    g_off[NN + 1];
__device__ int    g_csr[EE];
__device__ int    g_rank[EE];
__device__ float  g_dis[NN];
__device__ float  g_dis2[NN];
__device__ float  g_score[NN];
__device__ float  g_f[NN];             // score * dis2 (0 for masked)
__device__ float  g_p[NN];             // h . w_rel
__device__ float  g_hr[NN];            // h . w_root
__device__ float4 g_contrib[NN * 4];   // (x@W1) * dis  [N,16]
__device__ float4 g_h4[NN * 4];        // conv1 output  [N,16]
__device__ float4 g_gg[NN * 4];        // conv2 agg (pre-W2) [N,16]

// ---- thread-per-node scalar gather over one CSR bucket, table in SMEM ----
__device__ __forceinline__ float gather_sum_smem(const float* __restrict__ tab,
                                                 int beg, int end, int nbase) {
    float a0 = 0.f, a1 = 0.f, a2 = 0.f, a3 = 0.f;
    int i = beg;
    for (; i < end && (i & 3); i++) a0 += tab[__ldg(&g_csr[i]) - nbase];
    int n4 = (end - i) >> 2;
    const int4* c4 = (const int4*)&g_csr[i];
    for (int k = 0; k < n4; k++) {
        int4 u = __ldg(&c4[k]);
        a0 += tab[u.x - nbase];
        a1 += tab[u.y - nbase];
        a2 += tab[u.z - nbase];
        a3 += tab[u.w - nbase];
    }
    for (i += n4 << 2; i < end; i++) a0 += tab[__ldg(&g_csr[i]) - nbase];
    return (a0 + a1) + (a2 + a3);
}

// ============ CSR build: rank-capturing histogram + scan + atomic-free scatter ====
__global__ void __launch_bounds__(1024) k_build(const int* __restrict__ src,
                                                const int* __restrict__ dst) {
    __shared__ int sdeg[1024];
    __shared__ int soff[1024];
    int g = blockIdx.x, t = threadIdx.x;
    int ebase = g * EPG, nbase = g * NPER;
    sdeg[t] = 0;
    __syncthreads();
    for (int e = t; e < EPG; e += 1024) {
        int d = dst[ebase + e] - nbase;
        g_rank[ebase + e] = atomicAdd(&sdeg[d], 1);
    }
    __syncthreads();
    int v = sdeg[t];
    soff[t] = v;
    __syncthreads();
    for (int d = 1; d < 1024; d <<= 1) {
        int cur = soff[t];
        int add = (t >= d) ? soff[t - d] : 0;
        __syncthreads();
        soff[t] = cur + add;
        __syncthreads();
    }
    int excl = soff[t] - v;
    if (t < NPER) {
        g_off[nbase + t] = ebase + excl;
        g_dis[nbase + t] = rsqrtf((float)(v + 1));
    }
    if (g == NG - 1 && t == 0) g_off[NN] = EE;
    sdeg[t] = excl;
    __syncthreads();
    for (int e = t; e < EPG; e += 1024) {
        int d = dst[ebase + e] - nbase;
        g_csr[ebase + sdeg[d] + g_rank[ebase + e]] = src[ebase + e];
    }
}

// ============ GEMM1: contrib = (x @ W1) * dis ============
__global__ void k_gemm1(const float* __restrict__ x, const float* __restrict__ W1) {
    __shared__ float xs[64 * 129];
    __shared__ float ws[128 * 16];
    int tid = threadIdx.x;
    int v0 = blockIdx.x * 64;
    for (int i = tid; i < 2048; i += 256) ws[i] = W1[i];
    const float4* x4 = (const float4*)x;
    for (int i = tid; i < 64 * 32; i += 256) {
        int r = i >> 5, c = i & 31;
        int v = v0 + r;
        float4 val = (v < NN) ? x4[(size_t)v * 32 + c] : make_float4(0.f, 0.f, 0.f, 0.f);
        float* p = &xs[r * 129 + c * 4];
        p[0] = val.x; p[1] = val.y; p[2] = val.z; p[3] = val.w;
    }
    __syncthreads();
    int n = tid & 63;
    int jg = tid >> 6;
    float4 acc = make_float4(0.f, 0.f, 0.f, 0.f);
    const float4* ws4 = (const float4*)ws;
    const float* xr = &xs[n * 129];
#pragma unroll 8
    for (int k = 0; k < 128; k++) {
        float xv = xr[k];
        float4 w = ws4[k * 4 + jg];
        acc.x += xv * w.x; acc.y += xv * w.y; acc.z += xv * w.z; acc.w += xv * w.w;
    }
    int v = v0 + n;
    if (v < NN) {
        float d = g_dis[v];
        acc.x *= d; acc.y *= d; acc.z *= d; acc.w *= d;
        g_contrib[v * 4 + jg] = acc;
    }
}

// ============ conv1: scalar 16-lane SMEM gather (conflict-free); 4 blk/graph x 512 ====
__global__ void __launch_bounds__(512) k_conv1(const float* __restrict__ b1,
                                               const float* __restrict__ wrel,
                                               const float* __restrict__ wroot) {
    extern __shared__ float tile[];   // [1000][16]
    int g = blockIdx.x >> 2;
    int quarter = blockIdx.x & 3;
    int nbase = g * NPER;
    int tid = threadIdx.x;
    const float4* src4 = (const float4*)&g_contrib[nbase * 4];
    for (int i = tid; i < NPER * 4; i += 512) ((float4*)tile)[i] = src4[i];
    __syncthreads();
    int wid = tid >> 5, lane = tid & 31;
    int hh = lane >> 4, f = lane & 15;
    float bf = __ldg(&b1[f]);
    float wrf = __ldg(&wrel[f]);
    float wof = __ldg(&wroot[f]);
    int vbeg = quarter * 250, vend = vbeg + 250;
    for (int vl = vbeg + wid; vl < vend; vl += 16) {
        int v = nbase + vl;
        int beg = g_off[v], end = g_off[v + 1];
        float acc = 0.f;
        for (int i = beg + hh; i < end; i += 2) {
            int u = __ldg(&g_csr[i]) - nbase;
            acc += tile[u * 16 + f];
        }
        acc += __shfl_xor_sync(0xffffffffu, acc, 16);
        float d = g_dis[v];
        float hv = fmaxf(fmaf(d, acc + tile[vl * 16 + f], bf), 0.f);
        if (hh == 0) ((float*)g_h4)[v * 16 + f] = hv;
        float pp = hv * wrf;
        float rr = hv * wof;
#pragma unroll
        for (int m = 1; m < 16; m <<= 1) {
            pp += __shfl_xor_sync(0xffffffffu, pp, m);
            rr += __shfl_xor_sync(0xffffffffu, rr, m);
        }
        if (lane == 0) { g_p[v] = pp; g_hr[v] = rr; }
    }
}

// ============ score: thread-per-node, p-tile in SMEM; 2 blocks/graph x 512 ============
__global__ void __launch_bounds__(512) k_score(const float* __restrict__ brel) {
    __shared__ float p_s[NPER];
    int g = blockIdx.x >> 1;
    int half = blockIdx.x & 1;
    int nbase = g * NPER;
    int t = threadIdx.x;
    for (int i = t; i < NPER; i += 512) p_s[i] = g_p[nbase + i];
    __syncthreads();
    int vl = half * 500 + t;
    if (t < 500) {
        int v = nbase + vl;
        float s = gather_sum_smem(p_s, g_off[v], g_off[v + 1], nbase);
        g_score[v] = tanhf(s + g_hr[v] + __ldg(brel));
    }
}

// ============ top-K: hybrid bitonic + thread-per-node deg2 ============
__global__ void __launch_bounds__(1024) k_topk() {
    __shared__ unsigned long long keys[1024];
    __shared__ float smask[NPER];
    int g = blockIdx.x, t = threadIdx.x;
    int nbase = g * NPER;
    if (t < NPER) {
        unsigned u = __float_as_uint(g_score[nbase + t]);
        u = (u & 0x80000000u) ? ~u : (u | 0x80000000u);
        keys[t] = ((unsigned long long)u << 32) | (unsigned)(~t);  // ties: lower idx wins
    } else {
        keys[t] = 0ull;
    }
    __syncthreads();
    for (int k = 2; k <= 1024; k <<= 1) {
        for (int j = k >> 1; j >= 32; j >>= 1) {
            int ixj = t ^ j;
            if (ixj > t) {
                unsigned long long a = keys[t], b = keys[ixj];
                bool up = ((t & k) == 0);
                if ((a > b) == up) { keys[t] = b; keys[ixj] = a; }
            }
            __syncthreads();
        }
        unsigned long long v = keys[t];
        bool up = ((t & k) == 0);
        int jstart = (k >> 1 < 16) ? (k >> 1) : 16;
        for (int j = jstart; j > 0; j >>= 1) {
            unsigned long long o = __shfl_xor_sync(0xffffffffu, v, j);
            bool lower = ((t & j) == 0);
            bool keepmin = (lower == up);
            unsigned long long mn = (v < o) ? v : o;
            unsigned long long mx = (v < o) ? o : v;
            v = keepmin ? mn : mx;
        }
        keys[t] = v;
        __syncthreads();
    }
    if (t >= (1024 - NPER)) {
        unsigned idx = ~(unsigned)(keys[t] & 0xFFFFFFFFull);
        smask[idx] = (t >= 1024 - KTOP) ? 1.0f : 0.0f;
    }
    __syncthreads();
    if (t < NPER) {
        int v = nbase + t;
        float s = gather_sum_smem(smask, g_off[v], g_off[v + 1], nbase);
        float mv = smask[t];
        float d2 = (mv > 0.f) ? rsqrtf(mv + s) : 0.f;
        g_dis2[v] = d2;
        g_f[v] = g_score[v] * d2;
    }
}

// ============ conv2: PADDED c2 tile (rows of 5 float4 = 80B, conflict-free) ==========
__global__ void __launch_bounds__(512) k_conv2() {
    extern __shared__ float c2[];   // [1000*20] padded rows
    int g = blockIdx.x >> 2;
    int quarter = blockIdx.x & 3;
    int nbase = g * NPER;
    int t = threadIdx.x;
    const float4* h4 = (const float4*)&g_h4[nbase * 4];
    float4* c24 = (float4*)c2;
    for (int i = t; i < NPER * 4; i += 512) {
        int vl = i >> 2, c = i & 3;
        float f = __ldg(&g_f[nbase + vl]);
        float4 h = h4[i];
        c24[vl * 5 + c] = make_float4(h.x * f, h.y * f, h.z * f, h.w * f);
    }
    __syncthreads();
    int wid = t >> 5, lane = t & 31;
    int sub = lane >> 2, c = lane & 3;
    int vbeg = quarter * 250, vend = vbeg + 250;
    for (int vl = vbeg + wid; vl < vend; vl += 16) {
        int v = nbase + vl;
        float d2 = g_dis2[v];
        if (d2 == 0.f) continue;
        int beg = g_off[v], end = g_off[v + 1];
        float4 acc = make_float4(0.f, 0.f, 0.f, 0.f);
        for (int i = beg + sub; i < end; i += 8) {
            int u = __ldg(&g_csr[i]) - nbase;
            float4 tt = c24[u * 5 + c];        // padded: conflict-free banks
            acc.x += tt.x; acc.y += tt.y; acc.z += tt.z; acc.w += tt.w;
        }
#pragma unroll
        for (int m = 4; m < 32; m <<= 1) {
            acc.x += __shfl_xor_sync(0xffffffffu, acc.x, m);
            acc.y += __shfl_xor_sync(0xffffffffu, acc.y, m);
            acc.z += __shfl_xor_sync(0xffffffffu, acc.z, m);
            acc.w += __shfl_xor_sync(0xffffffffu, acc.w, m);
        }
        if (sub == 0) {
            float4 cv = c24[vl * 5 + c];
            g_gg[v * 4 + c] = make_float4(d2 * (acc.x + cv.x), d2 * (acc.y + cv.y),
                                          d2 * (acc.z + cv.z), d2 * (acc.w + cv.w));
        }
    }
}

// ============ fused GEMM2(16->256) + relu + masked mean pool (W2 in regs) ============
__global__ void k_pool(const float* __restrict__ W2, const float* __restrict__ b2,
                       float* __restrict__ out) {
    __shared__ float gs[16][16];
    __shared__ float ms[16];
    int t = threadIdx.x;
    int gi = blockIdx.x >> 3;
    int part = blockIdx.x & 7;
    int node0 = gi * NPER + part * 125;
    float w0[16], w1[16];
#pragma unroll
    for (int m = 0; m < 16; m++) {
        w0[m] = __ldg(&W2[m * 256 + t]);
        w1[m] = __ldg(&W2[m * 256 + t + 128]);
    }
    float bb0 = __ldg(&b2[t]), bb1 = __ldg(&b2[t + 128]);
    float acc0 = 0.f, acc1 = 0.f;
    const float* gflat = (const float*)g_gg;
    for (int base = 0; base < 125; base += 16) {
        int ns = min(16, 125 - base);
        for (int i = t; i < ns * 16; i += 128)
            ((float*)gs)[i] = gflat[(node0 + base) * 16 + i];
        if (t < ns) ms[t] = g_dis2[node0 + base + t];
        __syncthreads();
        for (int q = 0; q < ns; q++) {
            if (ms[q] != 0.f) {
                float s0 = bb0, s1 = bb1;
#pragma unroll
                for (int m = 0; m < 16; m++) {
                    float gv = gs[q][m];
                    s0 = fmaf(gv, w0[m], s0);
                    s1 = fmaf(gv, w1[m], s1);
                }
                acc0 += fmaxf(s0, 0.f);
                acc1 += fmaxf(s1, 0.f);
            }
        }
        __syncthreads();
    }
    const float inv = 1.0f / (float)KTOP;
    atomicAdd(&out[gi * 256 + t], acc0 * inv);
    atomicAdd(&out[gi * 256 + t + 128], acc1 * inv);
}

// ============ launch ============
extern "C" void kernel_launch(void* const* d_in, const int* in_sizes, int n_in,
                              void* d_out, int out_size) {
    const float* x     = (const float*)d_in[0];
    const int*   ei    = (const int*)d_in[1];
    const float* W1    = (const float*)d_in[3];
    const float* b1    = (const float*)d_in[4];
    const float* wrel  = (const float*)d_in[5];
    const float* brel  = (const float*)d_in[6];
    const float* wroot = (const float*)d_in[7];
    const float* W2    = (const float*)d_in[8];
    const float* b2    = (const float*)d_in[9];
    float* out = (float*)d_out;

    const int* src = ei;
    const int* dst = ei + EE;

    const int TILE_SMEM  = NPER * 16 * 4;   // 64000 (conv1)
    const int TILE2_SMEM = NPER * 20 * 4;   // 80000 (conv2, padded)
    cudaFuncSetAttribute(k_conv1, cudaFuncAttributeMaxDynamicSharedMemorySize, TILE_SMEM);
    cudaFuncSetAttribute(k_conv2, cudaFuncAttributeMaxDynamicSharedMemorySize, TILE2_SMEM);

    cudaMemsetAsync(d_out, 0, (size_t)out_size * sizeof(float), 0);

    k_build<<<NG, 1024>>>(src, dst);
    k_gemm1<<<(NN + 63) / 64, 256>>>(x, W1);
    k_conv1<<<NG * 4, 512, TILE_SMEM>>>(b1, wrel, wroot);
    k_score<<<NG * 2, 512>>>(brel);
    k_topk<<<NG, 1024>>>();
    k_conv2<<<NG * 4, 512, TILE2_SMEM>>>();
    k_pool<<<NG * 8, 128>>>(W2, b2, out);
}

// round 14
// speedup vs baseline: 1.2277x; 1.1297x over previous
#include <cuda_runtime.h>

#define NN 100000
#define EE 3200000
#define NG 100
#define NPER 1000
#define EPG 32000
#define KTOP 800

// ---------------- global scratch (static; no cudaMalloc) ----------------
__device__ int    g_off[NN + 1];
__device__ int    g_csr[EE];
__device__ float  g_dis[NN];
__device__ float  g_dis2[NN];
__device__ float  g_score[NN];
__device__ float  g_f[NN];             // score * dis2 (0 for masked)
__device__ float  g_p[NN];             // h . w_rel
__device__ float  g_hr[NN];            // h . w_root
__device__ float4 g_xw[NN * 4];        // x @ W1 (NO dis) [N,16]
__device__ float4 g_h4[NN * 4];        // conv1 output  [N,16]
__device__ float4 g_gg[NN * 4];        // conv2 agg (pre-W2) [N,16]

// ---- thread-per-node scalar gather over one CSR bucket, table in SMEM ----
__device__ __forceinline__ float gather_sum_smem(const float* __restrict__ tab,
                                                 int beg, int end, int nbase) {
    float a0 = 0.f, a1 = 0.f, a2 = 0.f, a3 = 0.f;
    int i = beg;
    for (; i < end && (i & 3); i++) a0 += tab[__ldg(&g_csr[i]) - nbase];
    int n4 = (end - i) >> 2;
    const int4* c4 = (const int4*)&g_csr[i];
    for (int k = 0; k < n4; k++) {
        int4 u = __ldg(&c4[k]);
        a0 += tab[u.x - nbase];
        a1 += tab[u.y - nbase];
        a2 += tab[u.z - nbase];
        a3 += tab[u.w - nbase];
    }
    for (i += n4 << 2; i < end; i++) a0 += tab[__ldg(&g_csr[i]) - nbase];
    return (a0 + a1) + (a2 + a3);
}

// ============ CSR build: register-cached ranks (no g_rank round-trip) ============
__global__ void __launch_bounds__(1024) k_build(const int* __restrict__ src,
                                                const int* __restrict__ dst) {
    __shared__ int sdeg[1024];
    __shared__ int soff[1024];
    int g = blockIdx.x, t = threadIdx.x;
    int ebase = g * EPG, nbase = g * NPER;
    sdeg[t] = 0;
    __syncthreads();
    unsigned pk[32];   // (rank<<16) | local_dst
#pragma unroll
    for (int k = 0; k < 32; k++) {
        int e = t + (k << 10);
        if (e < EPG) {
            int d = dst[ebase + e] - nbase;
            unsigned r = atomicAdd(&sdeg[d], 1);
            pk[k] = (r << 16) | (unsigned)d;
        }
    }
    __syncthreads();
    int v = sdeg[t];
    soff[t] = v;
    __syncthreads();
    for (int d = 1; d < 1024; d <<= 1) {
        int cur = soff[t];
        int add = (t >= d) ? soff[t - d] : 0;
        __syncthreads();
        soff[t] = cur + add;
        __syncthreads();
    }
    int excl = soff[t] - v;
    if (t < NPER) {
        g_off[nbase + t] = ebase + excl;
        g_dis[nbase + t] = rsqrtf((float)(v + 1));
    }
    if (g == NG - 1 && t == 0) g_off[NN] = EE;
    sdeg[t] = excl;
    __syncthreads();
#pragma unroll
    for (int k = 0; k < 32; k++) {
        int e = t + (k << 10);
        if (e < EPG) {
            unsigned p = pk[k];
            int d = p & 0xFFFFu;
            int r = (int)(p >> 16);
            g_csr[ebase + sdeg[d] + r] = src[ebase + e];
        }
    }
}

// ============ GEMM1: xw = x @ W1 (no dis -> independent of build) ============
__global__ void k_gemm1(const float* __restrict__ x, const float* __restrict__ W1) {
    __shared__ float xs[64 * 129];
    __shared__ float ws[128 * 16];
    int tid = threadIdx.x;
    int v0 = blockIdx.x * 64;
    for (int i = tid; i < 2048; i += 256) ws[i] = W1[i];
    const float4* x4 = (const float4*)x;
    for (int i = tid; i < 64 * 32; i += 256) {
        int r = i >> 5, c = i & 31;
        int v = v0 + r;
        float4 val = (v < NN) ? x4[(size_t)v * 32 + c] : make_float4(0.f, 0.f, 0.f, 0.f);
        float* p = &xs[r * 129 + c * 4];
        p[0] = val.x; p[1] = val.y; p[2] = val.z; p[3] = val.w;
    }
    __syncthreads();
    int n = tid & 63;
    int jg = tid >> 6;
    float4 acc = make_float4(0.f, 0.f, 0.f, 0.f);
    const float4* ws4 = (const float4*)ws;
    const float* xr = &xs[n * 129];
#pragma unroll 8
    for (int k = 0; k < 128; k++) {
        float xv = xr[k];
        float4 w = ws4[k * 4 + jg];
        acc.x += xv * w.x; acc.y += xv * w.y; acc.z += xv * w.z; acc.w += xv * w.w;
    }
    int v = v0 + n;
    if (v < NN) g_xw[v * 4 + jg] = acc;
}

// ============ conv1: scalar 16-lane SMEM gather; tile = xw*dis at load ============
__global__ void __launch_bounds__(512) k_conv1(const float* __restrict__ b1,
                                               const float* __restrict__ wrel,
                                               const float* __restrict__ wroot) {
    extern __shared__ float tile[];   // [1000][16] = xw * dis
    int g = blockIdx.x >> 2;
    int quarter = blockIdx.x & 3;
    int nbase = g * NPER;
    int tid = threadIdx.x;
    const float4* src4 = (const float4*)&g_xw[nbase * 4];
    float4* t4 = (float4*)tile;
    for (int i = tid; i < NPER * 4; i += 512) {
        int vl = i >> 2;
        float d = g_dis[nbase + vl];
        float4 val = src4[i];
        t4[i] = make_float4(val.x * d, val.y * d, val.z * d, val.w * d);
    }
    __syncthreads();
    int wid = tid >> 5, lane = tid & 31;
    int hh = lane >> 4, f = lane & 15;
    float bf = __ldg(&b1[f]);
    float wrf = __ldg(&wrel[f]);
    float wof = __ldg(&wroot[f]);
    int vbeg = quarter * 250, vend = vbeg + 250;
    for (int vl = vbeg + wid; vl < vend; vl += 16) {
        int v = nbase + vl;
        int beg = g_off[v], end = g_off[v + 1];
        float acc = 0.f;
        for (int i = beg + hh; i < end; i += 2) {
            int u = __ldg(&g_csr[i]) - nbase;
            acc += tile[u * 16 + f];
        }
        acc += __shfl_xor_sync(0xffffffffu, acc, 16);
        float d = g_dis[v];
        float hv = fmaxf(fmaf(d, acc + tile[vl * 16 + f], bf), 0.f);
        if (hh == 0) ((float*)g_h4)[v * 16 + f] = hv;
        float pp = hv * wrf;
        float rr = hv * wof;
#pragma unroll
        for (int m = 1; m < 16; m <<= 1) {
            pp += __shfl_xor_sync(0xffffffffu, pp, m);
            rr += __shfl_xor_sync(0xffffffffu, rr, m);
        }
        if (lane == 0) { g_p[v] = pp; g_hr[v] = rr; }
    }
}

// ============ score: thread-per-node, p-tile in SMEM; 2 blocks/graph x 512 ============
__global__ void __launch_bounds__(512) k_score(const float* __restrict__ brel) {
    __shared__ float p_s[NPER];
    int g = blockIdx.x >> 1;
    int half = blockIdx.x & 1;
    int nbase = g * NPER;
    int t = threadIdx.x;
    for (int i = t; i < NPER; i += 512) p_s[i] = g_p[nbase + i];
    __syncthreads();
    int vl = half * 500 + t;
    if (t < 500) {
        int v = nbase + vl;
        float s = gather_sum_smem(p_s, g_off[v], g_off[v + 1], nbase);
        g_score[v] = tanhf(s + g_hr[v] + __ldg(brel));
    }
}

// ============ top-K: hybrid bitonic + thread-per-node deg2 ============
__global__ void __launch_bounds__(1024) k_topk() {
    __shared__ unsigned long long keys[1024];
    __shared__ float smask[NPER];
    int g = blockIdx.x, t = threadIdx.x;
    int nbase = g * NPER;
    if (t < NPER) {
        unsigned u = __float_as_uint(g_score[nbase + t]);
        u = (u & 0x80000000u) ? ~u : (u | 0x80000000u);
        keys[t] = ((unsigned long long)u << 32) | (unsigned)(~t);  // ties: lower idx wins
    } else {
        keys[t] = 0ull;
    }
    __syncthreads();
    for (int k = 2; k <= 1024; k <<= 1) {
        for (int j = k >> 1; j >= 32; j >>= 1) {
            int ixj = t ^ j;
            if (ixj > t) {
                unsigned long long a = keys[t], b = keys[ixj];
                bool up = ((t & k) == 0);
                if ((a > b) == up) { keys[t] = b; keys[ixj] = a; }
            }
            __syncthreads();
        }
        unsigned long long v = keys[t];
        bool up = ((t & k) == 0);
        int jstart = (k >> 1 < 16) ? (k >> 1) : 16;
        for (int j = jstart; j > 0; j >>= 1) {
            unsigned long long o = __shfl_xor_sync(0xffffffffu, v, j);
            bool lower = ((t & j) == 0);
            bool keepmin = (lower == up);
            unsigned long long mn = (v < o) ? v : o;
            unsigned long long mx = (v < o) ? o : v;
            v = keepmin ? mn : mx;
        }
        keys[t] = v;
        __syncthreads();
    }
    if (t >= (1024 - NPER)) {
        unsigned idx = ~(unsigned)(keys[t] & 0xFFFFFFFFull);
        smask[idx] = (t >= 1024 - KTOP) ? 1.0f : 0.0f;
    }
    __syncthreads();
    if (t < NPER) {
        int v = nbase + t;
        float s = gather_sum_smem(smask, g_off[v], g_off[v + 1], nbase);
        float mv = smask[t];
        float d2 = (mv > 0.f) ? rsqrtf(mv + s) : 0.f;
        g_dis2[v] = d2;
        g_f[v] = g_score[v] * d2;
    }
}

// ============ conv2: 64KB c2-tile (unpadded, 3 blocks/SM), float4 gather ============
__global__ void __launch_bounds__(512) k_conv2() {
    extern __shared__ float c2[];   // [1000*16]
    int g = blockIdx.x >> 2;
    int quarter = blockIdx.x & 3;
    int nbase = g * NPER;
    int t = threadIdx.x;
    const float4* h4 = (const float4*)&g_h4[nbase * 4];
    float4* c24 = (float4*)c2;
    for (int i = t; i < NPER * 4; i += 512) {
        int vl = i >> 2;
        float f = __ldg(&g_f[nbase + vl]);
        float4 h = h4[i];
        c24[i] = make_float4(h.x * f, h.y * f, h.z * f, h.w * f);
    }
    __syncthreads();
    int wid = t >> 5, lane = t & 31;
    int sub = lane >> 2, c = lane & 3;
    int vbeg = quarter * 250, vend = vbeg + 250;
    for (int vl = vbeg + wid; vl < vend; vl += 16) {
        int v = nbase + vl;
        float d2 = g_dis2[v];
        if (d2 == 0.f) continue;
        int beg = g_off[v], end = g_off[v + 1];
        float4 acc = make_float4(0.f, 0.f, 0.f, 0.f);
        for (int i = beg + sub; i < end; i += 8) {
            int u = __ldg(&g_csr[i]) - nbase;
            float4 tt = c24[u * 4 + c];
            acc.x += tt.x; acc.y += tt.y; acc.z += tt.z; acc.w += tt.w;
        }
#pragma unroll
        for (int m = 4; m < 32; m <<= 1) {
            acc.x += __shfl_xor_sync(0xffffffffu, acc.x, m);
            acc.y += __shfl_xor_sync(0xffffffffu, acc.y, m);
            acc.z += __shfl_xor_sync(0xffffffffu, acc.z, m);
            acc.w += __shfl_xor_sync(0xffffffffu, acc.w, m);
        }
        if (sub == 0) {
            float4 cv = c24[vl * 4 + c];
            g_gg[v * 4 + c] = make_float4(d2 * (acc.x + cv.x), d2 * (acc.y + cv.y),
                                          d2 * (acc.z + cv.z), d2 * (acc.w + cv.w));
        }
    }
}

// ============ fused GEMM2(16->256) + relu + masked mean pool (W2 in regs) ============
__global__ void k_pool(const float* __restrict__ W2, const float* __restrict__ b2,
                       float* __restrict__ out) {
    __shared__ float gs[16][16];
    __shared__ float ms[16];
    int t = threadIdx.x;
    int gi = blockIdx.x >> 3;
    int part = blockIdx.x & 7;
    int node0 = gi * NPER + part * 125;
    float w0[16], w1[16];
#pragma unroll
    for (int m = 0; m < 16; m++) {
        w0[m] = __ldg(&W2[m * 256 + t]);
        w1[m] = __ldg(&W2[m * 256 + t + 128]);
    }
    float bb0 = __ldg(&b2[t]), bb1 = __ldg(&b2[t + 128]);
    float acc0 = 0.f, acc1 = 0.f;
    const float* gflat = (const float*)g_gg;
    for (int base = 0; base < 125; base += 16) {
        int ns = min(16, 125 - base);
        for (int i = t; i < ns * 16; i += 128)
            ((float*)gs)[i] = gflat[(node0 + base) * 16 + i];
        if (t < ns) ms[t] = g_dis2[node0 + base + t];
        __syncthreads();
        for (int q = 0; q < ns; q++) {
            if (ms[q] != 0.f) {
                float s0 = bb0, s1 = bb1;
#pragma unroll
                for (int m = 0; m < 16; m++) {
                    float gv = gs[q][m];
                    s0 = fmaf(gv, w0[m], s0);
                    s1 = fmaf(gv, w1[m], s1);
                }
                acc0 += fmaxf(s0, 0.f);
                acc1 += fmaxf(s1, 0.f);
            }
        }
        __syncthreads();
    }
    const float inv = 1.0f / (float)KTOP;
    atomicAdd(&out[gi * 256 + t], acc0 * inv);
    atomicAdd(&out[gi * 256 + t + 128], acc1 * inv);
}

// ============ launch: fork build || gemm1, join before conv1 ============
extern "C" void kernel_launch(void* const* d_in, const int* in_sizes, int n_in,
                              void* d_out, int out_size) {
    const float* x     = (const float*)d_in[0];
    const int*   ei    = (const int*)d_in[1];
    const float* W1    = (const float*)d_in[3];
    const float* b1    = (const float*)d_in[4];
    const float* wrel  = (const float*)d_in[5];
    const float* brel  = (const float*)d_in[6];
    const float* wroot = (const float*)d_in[7];
    const float* W2    = (const float*)d_in[8];
    const float* b2    = (const float*)d_in[9];
    float* out = (float*)d_out;

    const int* src = ei;
    const int* dst = ei + EE;

    // one-time host-side resources (created on the uncaptured correctness call)
    static cudaStream_t s2 = nullptr;
    static cudaEvent_t eFork = nullptr, eJoin = nullptr;
    if (s2 == nullptr) {
        cudaStreamCreateWithFlags(&s2, cudaStreamNonBlocking);
        cudaEventCreateWithFlags(&eFork, cudaEventDisableTiming);
        cudaEventCreateWithFlags(&eJoin, cudaEventDisableTiming);
        const int TILE_SMEM = NPER * 16 * 4;   // 64000
        cudaFuncSetAttribute(k_conv1, cudaFuncAttributeMaxDynamicSharedMemorySize, TILE_SMEM);
        cudaFuncSetAttribute(k_conv2, cudaFuncAttributeMaxDynamicSharedMemorySize, TILE_SMEM);
    }
    const int TILE_SMEM = NPER * 16 * 4;

    cudaMemsetAsync(d_out, 0, (size_t)out_size * sizeof(float), 0);

    // fork: gemm1 on s2 runs concurrently with build on the main stream
    cudaEventRecord(eFork, 0);
    cudaStreamWaitEvent(s2, eFork, 0);
    k_gemm1<<<(NN + 63) / 64, 256, 0, s2>>>(x, W1);
    cudaEventRecord(eJoin, s2);

    k_build<<<NG, 1024>>>(src, dst);

    // join: conv1 needs both csr/dis (build) and xw (gemm1)
    cudaStreamWaitEvent(0, eJoin, 0);

    k_conv1<<<NG * 4, 512, TILE_SMEM>>>(b1, wrel, wroot);
    k_score<<<NG * 2, 512>>>(brel);
    k_topk<<<NG, 1024>>>();
    k_conv2<<<NG * 4, 512, TILE_SMEM>>>();
    k_pool<<<NG * 8, 128>>>(W2, b2, out);
}